// round 3
// baseline (speedup 1.0000x reference)
#include <cuda_runtime.h>

#define NN 50000
#define NE 800000
#define D 256
#define DOUT 128
#define SCAN_B 49   // ceil(50000/1024)

// ---------------- device scratch (static: no allocation allowed) ----------------
__device__ float g_h0[NN * D];
__device__ float g_h1[NN * D];
__device__ float g_agg[NN * D];
__device__ float g_deginv[NN];
__device__ int   g_deg[NN];
__device__ int   g_rowptr[NN + 1];
__device__ int   g_cursor[NN];
__device__ int   g_col[NE];
__device__ int   g_bsum[SCAN_B];
__device__ int   g_is64;   // 1 if edge_index is int64, 0 if int32

// id: 0 -> g_h0, 1 -> g_h1, 2 -> g_agg, 3 -> external pointer
__device__ __forceinline__ float* bufptr(int id, float* ext) {
    if (id == 0) return g_h0;
    if (id == 1) return g_h1;
    if (id == 2) return g_agg;
    return ext;
}
__device__ __forceinline__ const float* cbufptr(int id, const float* ext) {
    if (id == 0) return g_h0;
    if (id == 1) return g_h1;
    if (id == 2) return g_agg;
    return ext;
}

// read edge endpoint (word = index into the logical [2*NE] array)
__device__ __forceinline__ int edge_at(const void* ei, int word) {
    if (g_is64) return (int)((const long long*)ei)[word];
    return ((const int*)ei)[word];
}

// ---------------- dtype probe: int64 storage => odd 32-bit words are zero high-halves ----------------
__global__ void k_detect(const int* __restrict__ ei32) {
    // single block, 512 threads; any nonzero odd word => int32
    __shared__ int nz;
    if (threadIdx.x == 0) nz = 0;
    __syncthreads();
    if (ei32[2 * threadIdx.x + 1] != 0) atomicOr(&nz, 1);
    __syncthreads();
    if (threadIdx.x == 0) g_is64 = nz ? 0 : 1;
}

// ---------------- CSR build ----------------
__global__ void k_zero_deg() {
    int i = blockIdx.x * blockDim.x + threadIdx.x;
    if (i < NN) g_deg[i] = 0;
}

__global__ void k_hist(const void* __restrict__ ei) {
    int e = blockIdx.x * blockDim.x + threadIdx.x;
    if (e < NE) {
        unsigned d = (unsigned)edge_at(ei, NE + e);
        if (d < NN) atomicAdd(&g_deg[d], 1);
    }
}

__global__ void k_scan1() {
    __shared__ int s[1024];
    int t = threadIdx.x;
    int i = blockIdx.x * 1024 + t;
    int v = (i < NN) ? g_deg[i] : 0;
    s[t] = v;
    __syncthreads();
    for (int o = 1; o < 1024; o <<= 1) {
        int a = (t >= o) ? s[t - o] : 0;
        __syncthreads();
        s[t] += a;
        __syncthreads();
    }
    if (i < NN) g_rowptr[i] = s[t] - v;   // block-local exclusive
    if (t == 1023) g_bsum[blockIdx.x] = s[1023];
}

__global__ void k_scan2() {
    int run = 0;
    for (int b = 0; b < SCAN_B; b++) {
        int t = g_bsum[b];
        g_bsum[b] = run;
        run += t;
    }
}

__global__ void k_scan3() {
    int i = blockIdx.x * blockDim.x + threadIdx.x;
    if (i < NN) {
        int rp = g_rowptr[i] + g_bsum[i >> 10];
        g_rowptr[i] = rp;
        g_cursor[i] = rp;
        int dg = g_deg[i];
        g_deginv[i] = 1.0f / (float)(dg > 0 ? dg : 1);
    }
    if (i == 0) g_rowptr[NN] = NE;
}

__global__ void k_fill(const void* __restrict__ ei) {
    int e = blockIdx.x * blockDim.x + threadIdx.x;
    if (e < NE) {
        unsigned d = (unsigned)edge_at(ei, NE + e);
        unsigned s = (unsigned)edge_at(ei, e);
        if (d < NN && s < NN) {
            int pos = atomicAdd(&g_cursor[d], 1);
            g_col[pos] = (int)s;
        }
    }
}

// ---------------- mean aggregation: g_agg[r] = mean over incoming src of hin[src] ----------------
__global__ void k_agg(const float* __restrict__ xext, int src_id) {
    const float* __restrict__ hin = cbufptr(src_id, xext);
    __shared__ int sc[256];
    int t = threadIdx.x;
    for (int r = blockIdx.x; r < NN; r += gridDim.x) {
        int beg = g_rowptr[r], end = g_rowptr[r + 1];
        float acc = 0.f;
        for (int base = beg; base < end; base += 256) {
            int cnt = min(256, end - base);
            __syncthreads();
            if (t < cnt) sc[t] = g_col[base + t];
            __syncthreads();
            int i = 0;
            for (; i + 4 <= cnt; i += 4) {
                float a0 = hin[(size_t)sc[i]     * D + t];
                float a1 = hin[(size_t)sc[i + 1] * D + t];
                float a2 = hin[(size_t)sc[i + 2] * D + t];
                float a3 = hin[(size_t)sc[i + 3] * D + t];
                acc += (a0 + a1) + (a2 + a3);
            }
            for (; i < cnt; i++) acc += hin[(size_t)sc[i] * D + t];
        }
        g_agg[(size_t)r * D + t] = acc * g_deginv[r];
    }
}

// ---------------- fp32 SMEM-tiled GEMM, optional dual source, fused bias(+relu) ----------------
// C[n, NC] = A@W (+ A2@W2) + bias, K = D = 256 per source.
__global__ __launch_bounds__(256, 2)
void k_gemm(int aid, int a2id, int cid,
            const float* __restrict__ aext, float* __restrict__ cext,
            const float* __restrict__ W,  const float* __restrict__ W2,
            const float* __restrict__ bias,
            int n, int NC, int relu, int dual) {
    const float* A  = cbufptr(aid, aext);
    const float* A2 = cbufptr(a2id, aext);
    float* C = bufptr(cid, cext);

    __shared__ float As[8][128];
    __shared__ float Bs[8][128];
    int tid = threadIdx.x;
    int bm = blockIdx.x * 128;
    int bn = blockIdx.y * 128;
    int tx = tid & 15, ty = tid >> 4;

    float acc[8][8];
#pragma unroll
    for (int i = 0; i < 8; i++)
#pragma unroll
        for (int j = 0; j < 8; j++) acc[i][j] = 0.f;

    int arow  = bm + (tid >> 1);
    int akoff = (tid & 1) * 4;
    int brow  = tid >> 5;
    int bcol  = (tid & 31) * 4;

    int nsrc = dual ? 2 : 1;
    for (int s = 0; s < nsrc; s++) {
        const float* Ap = s ? A2 : A;
        const float* Wp = s ? W2 : W;
        for (int k0 = 0; k0 < D; k0 += 8) {
            float4 av = make_float4(0.f, 0.f, 0.f, 0.f);
            if (arow < n) av = *(const float4*)(Ap + (size_t)arow * D + k0 + akoff);
            float4 bv = *(const float4*)(Wp + (size_t)(k0 + brow) * NC + bn + bcol);
            __syncthreads();
            As[akoff + 0][tid >> 1] = av.x;
            As[akoff + 1][tid >> 1] = av.y;
            As[akoff + 2][tid >> 1] = av.z;
            As[akoff + 3][tid >> 1] = av.w;
            *(float4*)&Bs[brow][bcol] = bv;
            __syncthreads();
#pragma unroll
            for (int kk = 0; kk < 8; kk++) {
                float a[8], b[8];
                float4 t0 = *(float4*)&As[kk][ty * 4];
                float4 t1 = *(float4*)&As[kk][64 + ty * 4];
                float4 u0 = *(float4*)&Bs[kk][tx * 4];
                float4 u1 = *(float4*)&Bs[kk][64 + tx * 4];
                a[0] = t0.x; a[1] = t0.y; a[2] = t0.z; a[3] = t0.w;
                a[4] = t1.x; a[5] = t1.y; a[6] = t1.z; a[7] = t1.w;
                b[0] = u0.x; b[1] = u0.y; b[2] = u0.z; b[3] = u0.w;
                b[4] = u1.x; b[5] = u1.y; b[6] = u1.z; b[7] = u1.w;
#pragma unroll
                for (int i = 0; i < 8; i++)
#pragma unroll
                    for (int j = 0; j < 8; j++)
                        acc[i][j] += a[i] * b[j];
            }
        }
    }

#pragma unroll
    for (int i = 0; i < 8; i++) {
        int m = bm + ((i < 4) ? (ty * 4 + i) : (64 + ty * 4 + i - 4));
        if (m >= n) continue;
#pragma unroll
        for (int j = 0; j < 8; j++) {
            int c = bn + ((j < 4) ? (tx * 4 + j) : (64 + tx * 4 + j - 4));
            float v = acc[i][j] + bias[c];
            if (relu) v = fmaxf(v, 0.f);
            C[(size_t)m * NC + c] = v;
        }
    }
}

// ---------------- row-wise log_softmax over 128 cols, in place ----------------
__global__ void k_lsm(float* __restrict__ out) {
    int r = blockIdx.x;
    int t = threadIdx.x;
    float v = out[(size_t)r * DOUT + t];
    __shared__ float smax[4], ssum[4];
    float m = v;
#pragma unroll
    for (int o = 16; o; o >>= 1) m = fmaxf(m, __shfl_xor_sync(0xffffffffu, m, o));
    if ((t & 31) == 0) smax[t >> 5] = m;
    __syncthreads();
    float mm = fmaxf(fmaxf(smax[0], smax[1]), fmaxf(smax[2], smax[3]));
    float e = expf(v - mm);
    float sum = e;
#pragma unroll
    for (int o = 16; o; o >>= 1) sum += __shfl_xor_sync(0xffffffffu, sum, o);
    if ((t & 31) == 0) ssum[t >> 5] = sum;
    __syncthreads();
    float tot = ssum[0] + ssum[1] + ssum[2] + ssum[3];
    out[(size_t)r * DOUT + t] = v - mm - logf(tot);
}

// ---------------- launch: kernel launches ONLY ----------------
extern "C" void kernel_launch(void* const* d_in, const int* in_sizes, int n_in,
                              void* d_out, int out_size) {
    const float* x  = (const float*)d_in[0];
    const void*  ei = d_in[1];
    const float* wl = (const float*)d_in[2];
    const float* bl = (const float*)d_in[3];
    const float* wr = (const float*)d_in[4];
    const float* w1 = (const float*)d_in[5];
    const float* b1 = (const float*)d_in[6];
    const float* w2 = (const float*)d_in[7];
    const float* b2 = (const float*)d_in[8];
    float* out = (float*)d_out;

    // edge_index dtype probe (int32 vs int64), then CSR by dst
    k_detect<<<1, 512>>>((const int*)ei);
    k_zero_deg<<<(NN + 255) / 256, 256>>>();
    k_hist<<<(NE + 255) / 256, 256>>>(ei);
    k_scan1<<<SCAN_B, 1024>>>();
    k_scan2<<<1, 1>>>();
    k_scan3<<<(NN + 255) / 256, 256>>>();
    k_fill<<<(NE + 255) / 256, 256>>>(ei);

    dim3 g2((NN + 127) / 128, 2);
    dim3 g1((NN + 127) / 128, 1);

    // layer 0: agg(x) ; h0 = relu(agg@wl0 + x@wr0 + bl0)
    k_agg<<<4096, 256>>>(x, 3);
    k_gemm<<<g2, 256>>>(2, 3, 0, x, nullptr,
                        wl + 0 * D * D, wr + 0 * D * D, bl + 0 * D, NN, D, 1, 1);
    // layer 1: agg(h0) ; h1 = relu(agg@wl1 + h0@wr1 + bl1)
    k_agg<<<4096, 256>>>(nullptr, 0);
    k_gemm<<<g2, 256>>>(2, 0, 1, nullptr, nullptr,
                        wl + 1 * D * D, wr + 1 * D * D, bl + 1 * D, NN, D, 1, 1);
    // layer 2: agg(h1) ; h0 = relu(agg@wl2 + h1@wr2 + bl2)
    k_agg<<<4096, 256>>>(nullptr, 1);
    k_gemm<<<g2, 256>>>(2, 1, 0, nullptr, nullptr,
                        wl + 2 * D * D, wr + 2 * D * D, bl + 2 * D, NN, D, 1, 1);

    // post_mp: g_agg = h0@w1 + b1 ; out = g_agg@w2 + b2 ; log_softmax
    k_gemm<<<g2, 256>>>(0, 0, 2, nullptr, nullptr, w1, nullptr, b1, NN, D, 0, 0);
    k_gemm<<<g1, 256>>>(2, 2, 3, nullptr, out, w2, nullptr, b2, NN, DOUT, 0, 0);
    k_lsm<<<NN, 128>>>(out);
}

// round 5
// speedup vs baseline: 1.3564x; 1.3564x over previous
#include <cuda_runtime.h>
#include <cuda_bf16.h>
#include <cstdint>

#define NN 50000
#define NE 800000
#define D 256
#define DOUT 128
#define SCAN_B 49   // ceil(50000/1024)

// ---------------- device scratch (static: no allocation allowed) ----------------
__device__ float g_hf0[NN * D];            // fp32 h copies (for aggregation reads)
__device__ float g_hf1[NN * D];
__device__ unsigned short g_xH[NN * D],   g_xL[NN * D];    // bf16 hi/lo pairs
__device__ unsigned short g_h0H[NN * D],  g_h0L[NN * D];
__device__ unsigned short g_h1H[NN * D],  g_h1L[NN * D];
__device__ unsigned short g_aggH[NN * D], g_aggL[NN * D];  // also reused as z in post_mp
__device__ unsigned short g_wtH[8 * 65536], g_wtL[8 * 65536]; // transposed+split weights
__device__ float g_deginv[NN];
__device__ int   g_deg[NN];
__device__ int   g_rowptr[NN + 1];
__device__ int   g_cursor[NN];
__device__ int   g_col[NE];
__device__ int   g_bsum[SCAN_B];
__device__ int   g_is64;

// pair ids: 0 -> x, 1 -> h0, 2 -> h1, 3 -> agg/z
__device__ __forceinline__ unsigned short* pairH(int id) {
    if (id == 0) return g_xH;
    if (id == 1) return g_h0H;
    if (id == 2) return g_h1H;
    return g_aggH;
}
__device__ __forceinline__ unsigned short* pairL(int id) {
    if (id == 0) return g_xL;
    if (id == 1) return g_h0L;
    if (id == 2) return g_h1L;
    return g_aggL;
}

__device__ __forceinline__ int edge_at(const void* ei, int word) {
    if (g_is64) return (int)((const long long*)ei)[word];
    return ((const int*)ei)[word];
}

__device__ __forceinline__ uint32_t smem_u32(const void* p) {
    uint32_t a;
    asm("{ .reg .u64 t; cvta.to.shared.u64 t, %1; cvt.u32.u64 %0, t; }" : "=r"(a) : "l"(p));
    return a;
}
__device__ __forceinline__ void ldm4(uint32_t addr, uint32_t& r0, uint32_t& r1,
                                     uint32_t& r2, uint32_t& r3) {
    asm volatile("ldmatrix.sync.aligned.m8n8.x4.shared.b16 {%0,%1,%2,%3}, [%4];"
                 : "=r"(r0), "=r"(r1), "=r"(r2), "=r"(r3) : "r"(addr));
}
__device__ __forceinline__ void mma16816(float* c, const uint32_t* a, const uint32_t* b) {
    asm volatile("mma.sync.aligned.m16n8k16.row.col.f32.bf16.bf16.f32 "
                 "{%0,%1,%2,%3}, {%4,%5,%6,%7}, {%8,%9}, {%0,%1,%2,%3};"
                 : "+f"(c[0]), "+f"(c[1]), "+f"(c[2]), "+f"(c[3])
                 : "r"(a[0]), "r"(a[1]), "r"(a[2]), "r"(a[3]), "r"(b[0]), "r"(b[1]));
}

// ---------------- splits ----------------
__global__ void k_split_x(const float* __restrict__ x) {
    int i = (blockIdx.x * blockDim.x + threadIdx.x) * 4;
    if (i >= NN * D) return;
#pragma unroll
    for (int j = 0; j < 4; j++) {
        float v = x[i + j];
        __nv_bfloat16 h = __float2bfloat16_rn(v);
        __nv_bfloat16 l = __float2bfloat16_rn(v - __bfloat162float(h));
        g_xH[i + j] = __bfloat16_as_ushort(h);
        g_xL[i + j] = __bfloat16_as_ushort(l);
    }
}

// transpose + split: WT[n][k] = W[k][n]; source W is [K, NC] row-major
__global__ void k_split_w(const float* __restrict__ W, int K, int NC, int off) {
    int t = blockIdx.x * blockDim.x + threadIdx.x;
    if (t >= K * NC) return;
    int k = t / NC, n = t % NC;
    float v = W[t];
    __nv_bfloat16 h = __float2bfloat16_rn(v);
    __nv_bfloat16 l = __float2bfloat16_rn(v - __bfloat162float(h));
    g_wtH[off + n * K + k] = __bfloat16_as_ushort(h);
    g_wtL[off + n * K + k] = __bfloat16_as_ushort(l);
}

// ---------------- dtype probe ----------------
__global__ void k_detect(const int* __restrict__ ei32) {
    __shared__ int nz;
    if (threadIdx.x == 0) nz = 0;
    __syncthreads();
    if (ei32[2 * threadIdx.x + 1] != 0) atomicOr(&nz, 1);
    __syncthreads();
    if (threadIdx.x == 0) g_is64 = nz ? 0 : 1;
}

// ---------------- CSR build ----------------
__global__ void k_zero_deg() {
    int i = blockIdx.x * blockDim.x + threadIdx.x;
    if (i < NN) g_deg[i] = 0;
}
__global__ void k_hist(const void* __restrict__ ei) {
    int e = blockIdx.x * blockDim.x + threadIdx.x;
    if (e < NE) {
        unsigned d = (unsigned)edge_at(ei, NE + e);
        if (d < NN) atomicAdd(&g_deg[d], 1);
    }
}
__global__ void k_scan1() {
    __shared__ int s[1024];
    int t = threadIdx.x;
    int i = blockIdx.x * 1024 + t;
    int v = (i < NN) ? g_deg[i] : 0;
    s[t] = v;
    __syncthreads();
    for (int o = 1; o < 1024; o <<= 1) {
        int a = (t >= o) ? s[t - o] : 0;
        __syncthreads();
        s[t] += a;
        __syncthreads();
    }
    if (i < NN) g_rowptr[i] = s[t] - v;
    if (t == 1023) g_bsum[blockIdx.x] = s[1023];
}
__global__ void k_scan2() {
    int run = 0;
    for (int b = 0; b < SCAN_B; b++) { int t = g_bsum[b]; g_bsum[b] = run; run += t; }
}
__global__ void k_scan3() {
    int i = blockIdx.x * blockDim.x + threadIdx.x;
    if (i < NN) {
        int rp = g_rowptr[i] + g_bsum[i >> 10];
        g_rowptr[i] = rp;
        g_cursor[i] = rp;
        int dg = g_deg[i];
        g_deginv[i] = 1.0f / (float)(dg > 0 ? dg : 1);
    }
    if (i == 0) g_rowptr[NN] = NE;
}
__global__ void k_fill(const void* __restrict__ ei) {
    int e = blockIdx.x * blockDim.x + threadIdx.x;
    if (e < NE) {
        unsigned d = (unsigned)edge_at(ei, NE + e);
        unsigned s = (unsigned)edge_at(ei, e);
        if (d < NN && s < NN) {
            int pos = atomicAdd(&g_cursor[d], 1);
            g_col[pos] = (int)s;
        }
    }
}

// ---------------- mean aggregation -> bf16 pair output ----------------
// src_id: 0 -> g_hf0, 1 -> g_hf1, 3 -> external x
__global__ void k_agg(const float* __restrict__ xext, int src_id) {
    const float* __restrict__ hin = (src_id == 0) ? g_hf0 : (src_id == 1) ? g_hf1 : xext;
    __shared__ int sc[256];
    int t = threadIdx.x;
    for (int r = blockIdx.x; r < NN; r += gridDim.x) {
        int beg = g_rowptr[r], end = g_rowptr[r + 1];
        float acc = 0.f;
        for (int base = beg; base < end; base += 256) {
            int cnt = min(256, end - base);
            __syncthreads();
            if (t < cnt) sc[t] = g_col[base + t];
            __syncthreads();
            int i = 0;
            for (; i + 4 <= cnt; i += 4) {
                float a0 = hin[(size_t)sc[i]     * D + t];
                float a1 = hin[(size_t)sc[i + 1] * D + t];
                float a2 = hin[(size_t)sc[i + 2] * D + t];
                float a3 = hin[(size_t)sc[i + 3] * D + t];
                acc += (a0 + a1) + (a2 + a3);
            }
            for (; i < cnt; i++) acc += hin[(size_t)sc[i] * D + t];
        }
        float v = acc * g_deginv[r];
        __nv_bfloat16 h = __float2bfloat16_rn(v);
        __nv_bfloat16 l = __float2bfloat16_rn(v - __bfloat162float(h));
        g_aggH[(size_t)r * D + t] = __bfloat16_as_ushort(h);
        g_aggL[(size_t)r * D + t] = __bfloat16_as_ushort(l);
    }
}

// ---------------- bf16-split tensor-core GEMM (mma.sync, sm_100-safe) ----------------
// C[128x128 tile] = sum_src (AH+AL)@(WH+WL)^T  (3 products), fused bias(+relu).
// outp: pair id (-1 none). f32sel: -1 none, 0 -> g_hf0, 1 -> g_hf1, 2 -> ext.
#define TROW 40            // padded row stride in bf16 elems (80 B)
#define TBYTES (128 * 80)  // 10240 B per tile

__global__ __launch_bounds__(256, 2)
void k_mma(int a1id, int a2id, int dual, int outp, int f32sel,
           float* __restrict__ cext, int woff1, int woff2,
           const float* __restrict__ bias, int relu, int ldc) {
    __shared__ __align__(16) unsigned char sT[4 * TBYTES];  // AH, AL, BH, BL
    uint32_t sb = smem_u32(sT);
    int tid = threadIdx.x;
    int lane = tid & 31;
    int wid = tid >> 5;
    int wm = wid & 1;        // 2 warp-rows  (64 rows each)
    int wn = wid >> 1;       // 4 warp-cols  (32 cols each)
    int bm = blockIdx.x * 128;
    int bn = blockIdx.y * 128;

    float acc[16][4];
#pragma unroll
    for (int i = 0; i < 16; i++)
#pragma unroll
        for (int j = 0; j < 4; j++) acc[i][j] = 0.f;

    // ldmatrix lane-address components
    int grp = lane >> 3, lr = lane & 7;
    // A-frag: row += (grp&1)*8, col += (grp&2)?8:0
    int a_r = wm * 64 + ((grp & 1) << 3) + lr;
    int a_c = (grp & 2) ? 8 : 0;
    // B-frag: row += (grp&2)?8:0, col += (grp&1)*8
    int b_r = wn * 32 + ((grp & 2) << 2) + lr;
    int b_c = (grp & 1) << 3;

    int nsrc = dual ? 2 : 1;
    for (int s = 0; s < nsrc; s++) {
        const unsigned short* gAH = s ? pairH(a2id) : pairH(a1id);
        const unsigned short* gAL = s ? pairL(a2id) : pairL(a1id);
        const unsigned short* gBH = g_wtH + (s ? woff2 : woff1);
        const unsigned short* gBL = g_wtL + (s ? woff2 : woff1);
        for (int kc = 0; kc < 8; kc++) {           // K chunks of 32
            __syncthreads();
            for (int u = tid; u < 2048; u += 256) {
                int tile = u >> 9;
                int row  = (u >> 2) & 127;
                int w    = u & 3;
                uint4 v = make_uint4(0, 0, 0, 0);
                if (tile < 2) {
                    int gr = bm + row;
                    if (gr < NN) {
                        const unsigned short* src = tile == 0 ? gAH : gAL;
                        v = *(const uint4*)(src + (size_t)gr * D + kc * 32 + w * 8);
                    }
                } else {
                    const unsigned short* src = tile == 2 ? gBH : gBL;
                    v = *(const uint4*)(src + (size_t)(bn + row) * D + kc * 32 + w * 8);
                }
                *(uint4*)(sT + tile * TBYTES + row * 80 + w * 16) = v;
            }
            __syncthreads();
#pragma unroll
            for (int kk = 0; kk < 32; kk += 16) {
                uint32_t bH[4][2], bL[4][2];
#pragma unroll
                for (int nb = 0; nb < 2; nb++) {   // two n16 halves of the 32-col warp tile
                    uint32_t off = (uint32_t)((b_r + nb * 16) * 80 + (kk + b_c) * 2);
                    uint32_t t0, t1, t2, t3;
                    ldm4(sb + 2 * TBYTES + off, t0, t1, t2, t3);
                    bH[nb * 2][0] = t0; bH[nb * 2][1] = t1;
                    bH[nb * 2 + 1][0] = t2; bH[nb * 2 + 1][1] = t3;
                    ldm4(sb + 3 * TBYTES + off, t0, t1, t2, t3);
                    bL[nb * 2][0] = t0; bL[nb * 2][1] = t1;
                    bL[nb * 2 + 1][0] = t2; bL[nb * 2 + 1][1] = t3;
                }
                uint32_t a[4];
#pragma unroll
                for (int mi = 0; mi < 4; mi++) {   // AH products
                    uint32_t off = (uint32_t)((a_r + mi * 16) * 80 + (kk + a_c) * 2);
                    ldm4(sb + off, a[0], a[1], a[2], a[3]);
#pragma unroll
                    for (int nj = 0; nj < 4; nj++) {
                        mma16816(acc[mi * 4 + nj], a, bH[nj]);
                        mma16816(acc[mi * 4 + nj], a, bL[nj]);
                    }
                }
#pragma unroll
                for (int mi = 0; mi < 4; mi++) {   // AL x BH
                    uint32_t off = (uint32_t)((a_r + mi * 16) * 80 + (kk + a_c) * 2);
                    ldm4(sb + TBYTES + off, a[0], a[1], a[2], a[3]);
#pragma unroll
                    for (int nj = 0; nj < 4; nj++)
                        mma16816(acc[mi * 4 + nj], a, bH[nj]);
                }
            }
        }
    }

    // epilogue
    unsigned short* oH = (outp >= 0) ? pairH(outp) : nullptr;
    unsigned short* oL = (outp >= 0) ? pairL(outp) : nullptr;
    float* f32d = (f32sel == 0) ? g_hf0 : (f32sel == 1) ? g_hf1 : cext;
#pragma unroll
    for (int mi = 0; mi < 4; mi++) {
#pragma unroll
        for (int nj = 0; nj < 4; nj++) {
            float* c = acc[mi * 4 + nj];
            int col = bn + wn * 32 + nj * 8 + (lane & 3) * 2;
            float bi0 = bias[col], bi1 = bias[col + 1];
#pragma unroll
            for (int half = 0; half < 2; half++) {
                int r = bm + wm * 64 + mi * 16 + (lane >> 2) + half * 8;
                if (r >= NN) continue;
                float v0 = c[half * 2] + bi0;
                float v1 = c[half * 2 + 1] + bi1;
                if (relu) { v0 = fmaxf(v0, 0.f); v1 = fmaxf(v1, 0.f); }
                if (oH) {
                    __nv_bfloat16 h0 = __float2bfloat16_rn(v0);
                    __nv_bfloat16 h1 = __float2bfloat16_rn(v1);
                    unsigned short l0 = __bfloat16_as_ushort(
                        __float2bfloat16_rn(v0 - __bfloat162float(h0)));
                    unsigned short l1 = __bfloat16_as_ushort(
                        __float2bfloat16_rn(v1 - __bfloat162float(h1)));
                    size_t base = (size_t)r * D + col;
                    *(ushort2*)(oH + base) =
                        make_ushort2(__bfloat16_as_ushort(h0), __bfloat16_as_ushort(h1));
                    *(ushort2*)(oL + base) = make_ushort2(l0, l1);
                }
                if (f32sel >= 0)
                    *(float2*)(f32d + (size_t)r * ldc + col) = make_float2(v0, v1);
            }
        }
    }
}

// ---------------- row-wise log_softmax over 128 cols, in place ----------------
__global__ void k_lsm(float* __restrict__ out) {
    int r = blockIdx.x;
    int t = threadIdx.x;
    float v = out[(size_t)r * DOUT + t];
    __shared__ float smax[4], ssum[4];
    float m = v;
#pragma unroll
    for (int o = 16; o; o >>= 1) m = fmaxf(m, __shfl_xor_sync(0xffffffffu, m, o));
    if ((t & 31) == 0) smax[t >> 5] = m;
    __syncthreads();
    float mm = fmaxf(fmaxf(smax[0], smax[1]), fmaxf(smax[2], smax[3]));
    float e = expf(v - mm);
    float sum = e;
#pragma unroll
    for (int o = 16; o; o >>= 1) sum += __shfl_xor_sync(0xffffffffu, sum, o);
    if ((t & 31) == 0) ssum[t >> 5] = sum;
    __syncthreads();
    float tot = ssum[0] + ssum[1] + ssum[2] + ssum[3];
    out[(size_t)r * DOUT + t] = v - mm - logf(tot);
}

// ---------------- launch: kernel launches ONLY ----------------
extern "C" void kernel_launch(void* const* d_in, const int* in_sizes, int n_in,
                              void* d_out, int out_size) {
    const float* x  = (const float*)d_in[0];
    const void*  ei = d_in[1];
    const float* wl = (const float*)d_in[2];
    const float* bl = (const float*)d_in[3];
    const float* wr = (const float*)d_in[4];
    const float* w1 = (const float*)d_in[5];
    const float* b1 = (const float*)d_in[6];
    const float* w2 = (const float*)d_in[7];
    const float* b2 = (const float*)d_in[8];
    float* out = (float*)d_out;

    // operand prep
    k_split_x<<<(NN * D / 4 + 255) / 256, 256>>>(x);
    for (int l = 0; l < 3; l++) {
        k_split_w<<<(D * D + 255) / 256, 256>>>(wl + (size_t)l * D * D, D, D, l * 65536);
        k_split_w<<<(D * D + 255) / 256, 256>>>(wr + (size_t)l * D * D, D, D, (3 + l) * 65536);
    }
    k_split_w<<<(D * D + 255) / 256, 256>>>(w1, D, D, 6 * 65536);
    k_split_w<<<(D * DOUT + 255) / 256, 256>>>(w2, D, DOUT, 7 * 65536);

    // CSR by dst
    k_detect<<<1, 512>>>((const int*)ei);
    k_zero_deg<<<(NN + 255) / 256, 256>>>();
    k_hist<<<(NE + 255) / 256, 256>>>(ei);
    k_scan1<<<SCAN_B, 1024>>>();
    k_scan2<<<1, 1>>>();
    k_scan3<<<(NN + 255) / 256, 256>>>();
    k_fill<<<(NE + 255) / 256, 256>>>(ei);

    dim3 g2((NN + 127) / 128, 2);
    dim3 g1((NN + 127) / 128, 1);

    // layer 0: agg(x); h0 = relu(agg@wl0 + x@wr0 + bl0)   (pair + fp32 copy -> g_hf0)
    k_agg<<<4096, 256>>>(x, 3);
    k_mma<<<g2, 256>>>(3, 0, 1, 1, 0, nullptr, 0 * 65536, 3 * 65536, bl + 0 * D, 1, D);
    // layer 1: agg(h0); h1 = relu(...)                    (pair + fp32 copy -> g_hf1)
    k_agg<<<4096, 256>>>(nullptr, 0);
    k_mma<<<g2, 256>>>(3, 1, 1, 2, 1, nullptr, 1 * 65536, 4 * 65536, bl + 1 * D, 1, D);
    // layer 2: agg(h1); h0 = relu(...)                    (pair only)
    k_agg<<<4096, 256>>>(nullptr, 1);
    k_mma<<<g2, 256>>>(3, 2, 1, 1, -1, nullptr, 2 * 65536, 5 * 65536, bl + 2 * D, 1, D);
    // post_mp: z = h0@w1 + b1 (pair -> agg bufs); out = z@w2 + b2 (fp32 ext)
    k_mma<<<g2, 256>>>(1, 1, 0, 3, -1, nullptr, 6 * 65536, 0, b1, 0, D);
    k_mma<<<g1, 256>>>(3, 3, 0, -1, 2, out, 7 * 65536, 0, b2, 0, DOUT);
    k_lsm<<<NN, 128>>>(out);
}

// round 6
// speedup vs baseline: 1.4761x; 1.0882x over previous
#include <cuda_runtime.h>
#include <cuda_bf16.h>
#include <cstdint>

#define NN 50000
#define NE 800000
#define D 256
#define DOUT 128
#define SCAN_B 49   // ceil(50000/1024)

// ---------------- device scratch (static: no allocation allowed) ----------------
__device__ float g_hf0[NN * D];            // fp32 h copies (for aggregation reads)
__device__ float g_hf1[NN * D];
__device__ unsigned short g_xH[NN * D],   g_xL[NN * D];    // bf16 hi/lo pairs
__device__ unsigned short g_h0H[NN * D],  g_h0L[NN * D];
__device__ unsigned short g_h1H[NN * D],  g_h1L[NN * D];
__device__ unsigned short g_aggH[NN * D], g_aggL[NN * D];  // also reused as z in post_mp
__device__ unsigned short g_wtH[8 * 65536], g_wtL[8 * 65536]; // transposed+split weights
__device__ float g_deginv[NN];
__device__ int   g_deg[NN];
__device__ int   g_rowptr[NN + 1];
__device__ int   g_cursor[NN];
__device__ int   g_col[NE];
__device__ int   g_bsum[SCAN_B];
__device__ int   g_is64;

// pair ids: 0 -> x, 1 -> h0, 2 -> h1, 3 -> agg/z
__device__ __forceinline__ unsigned short* pairH(int id) {
    if (id == 0) return g_xH;
    if (id == 1) return g_h0H;
    if (id == 2) return g_h1H;
    return g_aggH;
}
__device__ __forceinline__ unsigned short* pairL(int id) {
    if (id == 0) return g_xL;
    if (id == 1) return g_h0L;
    if (id == 2) return g_h1L;
    return g_aggL;
}

__device__ __forceinline__ int edge_at(const void* ei, int word) {
    if (g_is64) return (int)((const long long*)ei)[word];
    return ((const int*)ei)[word];
}

__device__ __forceinline__ uint32_t smem_u32(const void* p) {
    uint32_t a;
    asm("{ .reg .u64 t; cvta.to.shared.u64 t, %1; cvt.u32.u64 %0, t; }" : "=r"(a) : "l"(p));
    return a;
}
__device__ __forceinline__ void ldm4(uint32_t addr, uint32_t& r0, uint32_t& r1,
                                     uint32_t& r2, uint32_t& r3) {
    asm volatile("ldmatrix.sync.aligned.m8n8.x4.shared.b16 {%0,%1,%2,%3}, [%4];"
                 : "=r"(r0), "=r"(r1), "=r"(r2), "=r"(r3) : "r"(addr));
}
__device__ __forceinline__ void mma16816(float* c, const uint32_t* a, const uint32_t* b) {
    asm volatile("mma.sync.aligned.m16n8k16.row.col.f32.bf16.bf16.f32 "
                 "{%0,%1,%2,%3}, {%4,%5,%6,%7}, {%8,%9}, {%0,%1,%2,%3};"
                 : "+f"(c[0]), "+f"(c[1]), "+f"(c[2]), "+f"(c[3])
                 : "r"(a[0]), "r"(a[1]), "r"(a[2]), "r"(a[3]), "r"(b[0]), "r"(b[1]));
}
__device__ __forceinline__ void cpa16(uint32_t dst, const void* src, int valid) {
    asm volatile("cp.async.ca.shared.global [%0], [%1], 16, %2;"
                 :: "r"(dst), "l"(src), "r"(valid ? 16 : 0));
}
#define CP_COMMIT() asm volatile("cp.async.commit_group;" ::: "memory")
#define CP_WAIT1()  asm volatile("cp.async.wait_group 1;" ::: "memory")
#define CP_WAIT0()  asm volatile("cp.async.wait_group 0;" ::: "memory")

// ---------------- splits ----------------
__global__ void k_split_x(const float* __restrict__ x) {
    int i = (blockIdx.x * blockDim.x + threadIdx.x) * 4;
    if (i >= NN * D) return;
#pragma unroll
    for (int j = 0; j < 4; j++) {
        float v = x[i + j];
        __nv_bfloat16 h = __float2bfloat16_rn(v);
        __nv_bfloat16 l = __float2bfloat16_rn(v - __bfloat162float(h));
        g_xH[i + j] = __bfloat16_as_ushort(h);
        g_xL[i + j] = __bfloat16_as_ushort(l);
    }
}

// transpose + split: WT[n][k] = W[k][n]; source W is [K, NC] row-major
__global__ void k_split_w(const float* __restrict__ W, int K, int NC, int off) {
    int t = blockIdx.x * blockDim.x + threadIdx.x;
    if (t >= K * NC) return;
    int k = t / NC, n = t % NC;
    float v = W[t];
    __nv_bfloat16 h = __float2bfloat16_rn(v);
    __nv_bfloat16 l = __float2bfloat16_rn(v - __bfloat162float(h));
    g_wtH[off + n * K + k] = __bfloat16_as_ushort(h);
    g_wtL[off + n * K + k] = __bfloat16_as_ushort(l);
}

// ---------------- dtype probe ----------------
__global__ void k_detect(const int* __restrict__ ei32) {
    __shared__ int nz;
    if (threadIdx.x == 0) nz = 0;
    __syncthreads();
    if (ei32[2 * threadIdx.x + 1] != 0) atomicOr(&nz, 1);
    __syncthreads();
    if (threadIdx.x == 0) g_is64 = nz ? 0 : 1;
}

// ---------------- CSR build ----------------
__global__ void k_zero_deg() {
    int i = blockIdx.x * blockDim.x + threadIdx.x;
    if (i < NN) g_deg[i] = 0;
}
__global__ void k_hist(const void* __restrict__ ei) {
    int e = blockIdx.x * blockDim.x + threadIdx.x;
    if (e < NE) {
        unsigned d = (unsigned)edge_at(ei, NE + e);
        if (d < NN) atomicAdd(&g_deg[d], 1);
    }
}
__global__ void k_scan1() {
    __shared__ int s[1024];
    int t = threadIdx.x;
    int i = blockIdx.x * 1024 + t;
    int v = (i < NN) ? g_deg[i] : 0;
    s[t] = v;
    __syncthreads();
    for (int o = 1; o < 1024; o <<= 1) {
        int a = (t >= o) ? s[t - o] : 0;
        __syncthreads();
        s[t] += a;
        __syncthreads();
    }
    if (i < NN) g_rowptr[i] = s[t] - v;
    if (t == 1023) g_bsum[blockIdx.x] = s[1023];
}
__global__ void k_scan2() {
    int run = 0;
    for (int b = 0; b < SCAN_B; b++) { int t = g_bsum[b]; g_bsum[b] = run; run += t; }
}
__global__ void k_scan3() {
    int i = blockIdx.x * blockDim.x + threadIdx.x;
    if (i < NN) {
        int rp = g_rowptr[i] + g_bsum[i >> 10];
        g_rowptr[i] = rp;
        g_cursor[i] = rp;
        int dg = g_deg[i];
        g_deginv[i] = 1.0f / (float)(dg > 0 ? dg : 1);
    }
    if (i == 0) g_rowptr[NN] = NE;
}
__global__ void k_fill(const void* __restrict__ ei) {
    int e = blockIdx.x * blockDim.x + threadIdx.x;
    if (e < NE) {
        unsigned d = (unsigned)edge_at(ei, NE + e);
        unsigned s = (unsigned)edge_at(ei, e);
        if (d < NN && s < NN) {
            int pos = atomicAdd(&g_cursor[d], 1);
            g_col[pos] = (int)s;
        }
    }
}

// ---------------- mean aggregation -> bf16 pair output ----------------
// src_id: 0 -> g_hf0, 1 -> g_hf1, 3 -> external x
__global__ void k_agg(const float* __restrict__ xext, int src_id) {
    const float* __restrict__ hin = (src_id == 0) ? g_hf0 : (src_id == 1) ? g_hf1 : xext;
    __shared__ int sc[256];
    int t = threadIdx.x;
    for (int r = blockIdx.x; r < NN; r += gridDim.x) {
        int beg = g_rowptr[r], end = g_rowptr[r + 1];
        float acc = 0.f;
        for (int base = beg; base < end; base += 256) {
            int cnt = min(256, end - base);
            __syncthreads();
            if (t < cnt) sc[t] = g_col[base + t];
            __syncthreads();
            int i = 0;
            for (; i + 4 <= cnt; i += 4) {
                float a0 = hin[(size_t)sc[i]     * D + t];
                float a1 = hin[(size_t)sc[i + 1] * D + t];
                float a2 = hin[(size_t)sc[i + 2] * D + t];
                float a3 = hin[(size_t)sc[i + 3] * D + t];
                acc += (a0 + a1) + (a2 + a3);
            }
            for (; i < cnt; i++) acc += hin[(size_t)sc[i] * D + t];
        }
        float v = acc * g_deginv[r];
        __nv_bfloat16 h = __float2bfloat16_rn(v);
        __nv_bfloat16 l = __float2bfloat16_rn(v - __bfloat162float(h));
        g_aggH[(size_t)r * D + t] = __bfloat16_as_ushort(h);
        g_aggL[(size_t)r * D + t] = __bfloat16_as_ushort(l);
    }
}

// ---------------- bf16-split tensor-core GEMM, cp.async double-buffered ----------------
// C[128x128 tile] = sum_src (AH+AL)@(WH+WL)^T  (3 products), fused bias(+relu).
// K-chunk 16; tiles AH/AL/BH/BL 128 rows x 16 bf16, padded to 48 B rows (conflict-free).
#define TROWB   48
#define TILE_B  (128 * TROWB)       // 6144
#define STAGE_B (4 * TILE_B)        // 24576

__global__ __launch_bounds__(256, 2)
void k_mma(int a1id, int a2id, int dual, int outp, int f32sel,
           float* __restrict__ cext, int woff1, int woff2,
           const float* __restrict__ bias, int relu, int ldc) {
    __shared__ __align__(16) unsigned char sT[2 * STAGE_B];  // 48 KB
    uint32_t sb = smem_u32(sT);
    int tid = threadIdx.x;
    int lane = tid & 31;
    int wid = tid >> 5;
    int wm = wid & 1;        // 2 warp-rows (64 rows)
    int wn = wid >> 1;       // 4 warp-cols (32 cols)
    int bm = blockIdx.x * 128;
    int bn = blockIdx.y * 128;

    const unsigned short* pAH[2] = { pairH(a1id), pairH(a2id) };
    const unsigned short* pAL[2] = { pairL(a1id), pairL(a2id) };
    const unsigned short* pBH[2] = { g_wtH + woff1, g_wtH + woff2 };
    const unsigned short* pBL[2] = { g_wtL + woff1, g_wtL + woff2 };

    float acc[16][4];
#pragma unroll
    for (int i = 0; i < 16; i++)
#pragma unroll
        for (int j = 0; j < 4; j++) acc[i][j] = 0.f;

    // loader mapping: each thread fills one 16B segment per tile per stage
    int lrow = tid >> 1, seg = tid & 1;
    int gr = bm + lrow;
    int av = gr < NN;
    size_t aoff = (size_t)(av ? gr : 0) * D + seg * 8;
    size_t boff = (size_t)(bn + lrow) * D + seg * 8;
    uint32_t dbase = sb + (uint32_t)(lrow * TROWB + seg * 16);

    // ldmatrix lane-address components (round-5 proven mapping, stride 48)
    int grp = lane >> 3, lr = lane & 7;
    int a_r = wm * 64 + ((grp & 1) << 3) + lr;
    int a_c = (grp & 2) ? 8 : 0;
    int b_r = wn * 32 + ((grp & 2) << 2) + lr;
    int b_c = (grp & 1) << 3;
    uint32_t offA = (uint32_t)(a_r * TROWB + a_c * 2);
    uint32_t offB = (uint32_t)(b_r * TROWB + b_c * 2);

    int NIT = dual ? 32 : 16;

    // prologue: stage 0 <- iteration 0
    {
        cpa16(dbase,              pAH[0] + aoff, av);
        cpa16(dbase + TILE_B,     pAL[0] + aoff, av);
        cpa16(dbase + 2 * TILE_B, pBH[0] + boff, 1);
        cpa16(dbase + 3 * TILE_B, pBL[0] + boff, 1);
        CP_COMMIT();
    }

    for (int it = 0; it < NIT; it++) {
        if (it + 1 < NIT) {
            int s  = (it + 1) >> 4;
            int kc = (it + 1) & 15;
            uint32_t d = dbase + (uint32_t)(((it + 1) & 1) * STAGE_B);
            cpa16(d,              pAH[s] + aoff + kc * 16, av);
            cpa16(d + TILE_B,     pAL[s] + aoff + kc * 16, av);
            cpa16(d + 2 * TILE_B, pBH[s] + boff + kc * 16, 1);
            cpa16(d + 3 * TILE_B, pBL[s] + boff + kc * 16, 1);
            CP_COMMIT();
            CP_WAIT1();
        } else {
            CP_WAIT0();
        }
        __syncthreads();

        uint32_t base = sb + (uint32_t)((it & 1) * STAGE_B);
        uint32_t bH[4][2], bL[4][2];
#pragma unroll
        for (int nb = 0; nb < 2; nb++) {
            uint32_t off = offB + (uint32_t)(nb * 16 * TROWB);
            uint32_t t0, t1, t2, t3;
            ldm4(base + 2 * TILE_B + off, t0, t1, t2, t3);
            bH[nb * 2][0] = t0; bH[nb * 2][1] = t1;
            bH[nb * 2 + 1][0] = t2; bH[nb * 2 + 1][1] = t3;
            ldm4(base + 3 * TILE_B + off, t0, t1, t2, t3);
            bL[nb * 2][0] = t0; bL[nb * 2][1] = t1;
            bL[nb * 2 + 1][0] = t2; bL[nb * 2 + 1][1] = t3;
        }
        uint32_t a[4];
#pragma unroll
        for (int mi = 0; mi < 4; mi++) {
            uint32_t off = offA + (uint32_t)(mi * 16 * TROWB);
            ldm4(base + off, a[0], a[1], a[2], a[3]);
#pragma unroll
            for (int nj = 0; nj < 4; nj++) {
                mma16816(acc[mi * 4 + nj], a, bH[nj]);
                mma16816(acc[mi * 4 + nj], a, bL[nj]);
            }
            ldm4(base + TILE_B + off, a[0], a[1], a[2], a[3]);
#pragma unroll
            for (int nj = 0; nj < 4; nj++)
                mma16816(acc[mi * 4 + nj], a, bH[nj]);
        }
        __syncthreads();
    }

    // epilogue (round-5 proven)
    unsigned short* oH = (outp >= 0) ? pairH(outp) : nullptr;
    unsigned short* oL = (outp >= 0) ? pairL(outp) : nullptr;
    float* f32d = (f32sel == 0) ? g_hf0 : (f32sel == 1) ? g_hf1 : cext;
#pragma unroll
    for (int mi = 0; mi < 4; mi++) {
#pragma unroll
        for (int nj = 0; nj < 4; nj++) {
            float* c = acc[mi * 4 + nj];
            int col = bn + wn * 32 + nj * 8 + (lane & 3) * 2;
            float bi0 = bias[col], bi1 = bias[col + 1];
#pragma unroll
            for (int half = 0; half < 2; half++) {
                int r = bm + wm * 64 + mi * 16 + (lane >> 2) + half * 8;
                if (r >= NN) continue;
                float v0 = c[half * 2] + bi0;
                float v1 = c[half * 2 + 1] + bi1;
                if (relu) { v0 = fmaxf(v0, 0.f); v1 = fmaxf(v1, 0.f); }
                if (oH) {
                    __nv_bfloat16 h0 = __float2bfloat16_rn(v0);
                    __nv_bfloat16 h1 = __float2bfloat16_rn(v1);
                    unsigned short l0 = __bfloat16_as_ushort(
                        __float2bfloat16_rn(v0 - __bfloat162float(h0)));
                    unsigned short l1 = __bfloat16_as_ushort(
                        __float2bfloat16_rn(v1 - __bfloat162float(h1)));
                    size_t base = (size_t)r * D + col;
                    *(ushort2*)(oH + base) =
                        make_ushort2(__bfloat16_as_ushort(h0), __bfloat16_as_ushort(h1));
                    *(ushort2*)(oL + base) = make_ushort2(l0, l1);
                }
                if (f32sel >= 0)
                    *(float2*)(f32d + (size_t)r * ldc + col) = make_float2(v0, v1);
            }
        }
    }
}

// ---------------- row-wise log_softmax over 128 cols, in place ----------------
__global__ void k_lsm(float* __restrict__ out) {
    int r = blockIdx.x;
    int t = threadIdx.x;
    float v = out[(size_t)r * DOUT + t];
    __shared__ float smax[4], ssum[4];
    float m = v;
#pragma unroll
    for (int o = 16; o; o >>= 1) m = fmaxf(m, __shfl_xor_sync(0xffffffffu, m, o));
    if ((t & 31) == 0) smax[t >> 5] = m;
    __syncthreads();
    float mm = fmaxf(fmaxf(smax[0], smax[1]), fmaxf(smax[2], smax[3]));
    float e = expf(v - mm);
    float sum = e;
#pragma unroll
    for (int o = 16; o; o >>= 1) sum += __shfl_xor_sync(0xffffffffu, sum, o);
    if ((t & 31) == 0) ssum[t >> 5] = sum;
    __syncthreads();
    float tot = ssum[0] + ssum[1] + ssum[2] + ssum[3];
    out[(size_t)r * DOUT + t] = v - mm - logf(tot);
}

// ---------------- launch: kernel launches ONLY ----------------
extern "C" void kernel_launch(void* const* d_in, const int* in_sizes, int n_in,
                              void* d_out, int out_size) {
    const float* x  = (const float*)d_in[0];
    const void*  ei = d_in[1];
    const float* wl = (const float*)d_in[2];
    const float* bl = (const float*)d_in[3];
    const float* wr = (const float*)d_in[4];
    const float* w1 = (const float*)d_in[5];
    const float* b1 = (const float*)d_in[6];
    const float* w2 = (const float*)d_in[7];
    const float* b2 = (const float*)d_in[8];
    float* out = (float*)d_out;

    // operand prep
    k_split_x<<<(NN * D / 4 + 255) / 256, 256>>>(x);
    for (int l = 0; l < 3; l++) {
        k_split_w<<<(D * D + 255) / 256, 256>>>(wl + (size_t)l * D * D, D, D, l * 65536);
        k_split_w<<<(D * D + 255) / 256, 256>>>(wr + (size_t)l * D * D, D, D, (3 + l) * 65536);
    }
    k_split_w<<<(D * D + 255) / 256, 256>>>(w1, D, D, 6 * 65536);
    k_split_w<<<(D * DOUT + 255) / 256, 256>>>(w2, D, DOUT, 7 * 65536);

    // CSR by dst
    k_detect<<<1, 512>>>((const int*)ei);
    k_zero_deg<<<(NN + 255) / 256, 256>>>();
    k_hist<<<(NE + 255) / 256, 256>>>(ei);
    k_scan1<<<SCAN_B, 1024>>>();
    k_scan2<<<1, 1>>>();
    k_scan3<<<(NN + 255) / 256, 256>>>();
    k_fill<<<(NE + 255) / 256, 256>>>(ei);

    dim3 g2((NN + 127) / 128, 2);
    dim3 g1((NN + 127) / 128, 1);

    // layer 0: agg(x); h0 = relu(agg@wl0 + x@wr0 + bl0)   (pair + fp32 copy -> g_hf0)
    k_agg<<<4096, 256>>>(x, 3);
    k_mma<<<g2, 256>>>(3, 0, 1, 1, 0, nullptr, 0 * 65536, 3 * 65536, bl + 0 * D, 1, D);
    // layer 1: agg(h0); h1 = relu(...)                    (pair + fp32 copy -> g_hf1)
    k_agg<<<4096, 256>>>(nullptr, 0);
    k_mma<<<g2, 256>>>(3, 1, 1, 2, 1, nullptr, 1 * 65536, 4 * 65536, bl + 1 * D, 1, D);
    // layer 2: agg(h1); h0 = relu(...)                    (pair only)
    k_agg<<<4096, 256>>>(nullptr, 1);
    k_mma<<<g2, 256>>>(3, 2, 1, 1, -1, nullptr, 2 * 65536, 5 * 65536, bl + 2 * D, 1, D);
    // post_mp: z = h0@w1 + b1 (pair -> agg bufs); out = z@w2 + b2 (fp32 ext)
    k_mma<<<g2, 256>>>(1, 1, 0, 3, -1, nullptr, 6 * 65536, 0, b1, 0, D);
    k_mma<<<g1, 256>>>(3, 3, 0, -1, 2, out, 7 * 65536, 0, b2, 0, DOUT);
    k_lsm<<<NN, 128>>>(out);
}